// round 10
// baseline (speedup 1.0000x reference)
#include <cuda_runtime.h>

#define N_NODES 100000
#define N_EDGES 1600000
#define D 128
#define A_DIM 512
#define G_NUM 64

// tall GEMM config: NBLK * KC == N_NODES exactly
#define NBLK 800
#define KC 125
#define TK 25
#define NT (KC / TK)   // 5 tiles per block

// ---------------- scratch (device globals) ----------------
__device__ int   g_cnt[N_NODES];
__device__ float g_dis[N_NODES];
__device__ __align__(16) int2  g_db[N_NODES];        // {batch[i], dis[i] as int}
__device__ __align__(16) float g_xn[N_NODES * 4];    // x[i]*dis[i], w = 0
__device__ __align__(16) float g_agg3[N_NODES * 4];  // {self+sum xn, w = dis[i]}
__device__ __align__(16) float g_C[N_NODES * G_NUM]; // Craw[k][g]
__device__ __align__(16) float g_T[G_NUM * D];       // atomically reduced result
__device__ int   g_cntg[G_NUM];

// ---------------- helpers ----------------
__device__ __forceinline__ unsigned long long packf2(float v) {
    unsigned long long r;
    unsigned int u = __float_as_uint(v);
    asm("mov.b64 %0, {%1, %1};" : "=l"(r) : "r"(u));
    return r;
}
__device__ __forceinline__ void fma2(unsigned long long& d, unsigned long long a,
                                     unsigned long long b) {
    asm("fma.rn.f32x2 %0, %1, %2, %0;" : "+l"(d) : "l"(a), "l"(b));
}
__device__ __forceinline__ void red_add_v4(float* p, float4 v) {
    unsigned long long gp = (unsigned long long)__cvta_generic_to_global(p);
    asm volatile("red.global.add.v4.f32 [%0], {%1,%2,%3,%4};"
                 :: "l"(gp), "f"(v.x), "f"(v.y), "f"(v.z), "f"(v.w) : "memory");
}
__device__ __forceinline__ void cpa16(void* smem, const void* g) {
    unsigned s = (unsigned)__cvta_generic_to_shared(smem);
    unsigned long long ga = (unsigned long long)__cvta_generic_to_global(g);
    asm volatile("cp.async.ca.shared.global [%0], [%1], 16;" :: "r"(s), "l"(ga));
}
#define CP_COMMIT() asm volatile("cp.async.commit_group;" ::: "memory")
#define CP_WAIT0()  asm volatile("cp.async.wait_group 0;" ::: "memory")

// ---------------- degree histogram ----------------
__global__ void k_hist(const int* __restrict__ dst) {
    int e = blockIdx.x * blockDim.x + threadIdx.x;
    if (e < N_EDGES) atomicAdd(&g_cnt[dst[e]], 1);
}

// ---------------- fused init: C rows (single touch, self term) + per-node state ----------------
__global__ void k_dis_init(const float* __restrict__ x, const int* __restrict__ batch) {
    int idx = blockIdx.x * blockDim.x + threadIdx.x;   // over N_NODES*16 float4 slots
    if (idx >= N_NODES * 16) return;
    int node = idx >> 4;
    int slot = idx & 15;
    float dv = rsqrtf((float)(g_cnt[node] + 1));
    int b = batch[node];
    float4 v = make_float4(0.f, 0.f, 0.f, 0.f);
    int gbase = slot * 4;
    if (b - gbase == 0) v.x = dv;
    else if (b - gbase == 1) v.y = dv;
    else if (b - gbase == 2) v.z = dv;
    else if (b - gbase == 3) v.w = dv;
    ((float4*)g_C)[idx] = v;
    if (slot == 0) {
        g_dis[node] = dv;
        g_db[node] = make_int2(b, __float_as_int(dv));
        float xa = x[node * 3 + 0] * dv;
        float xb = x[node * 3 + 1] * dv;
        float xc = x[node * 3 + 2] * dv;
        ((float4*)g_xn)[node]   = make_float4(xa, xb, xc, 0.0f);
        ((float4*)g_agg3)[node] = make_float4(xa, xb, xc, dv);   // w carries dis
        atomicAdd(&g_cntg[b], 1);
    }
}

// ---------------- per-edge: agg3[d].xyz += xn[s].xyz (w += 0);  Craw[s][batch[d]] += dis[d] ----------------
__global__ void k_edge(const int* __restrict__ src, const int* __restrict__ dst) {
    int e = blockIdx.x * blockDim.x + threadIdx.x;
    if (e >= N_EDGES) return;
    int s = src[e];
    int d = dst[e];
    int2 db = g_db[d];
    float disd = __int_as_float(db.y);
    float4 v = ((const float4*)g_xn)[s];          // w = 0, preserves agg3.w = dis
    red_add_v4(&g_agg3[d * 4], v);
    atomicAdd(&g_C[s * G_NUM + db.x], disd);
}

// ---------------- pipelined fused tall GEMM (128 threads, 8g x 8f, 5 blocks/SM) ----------------
// g_T[g][f] += sum_k Craw[k][g] * (dis[k]*h1r[k][f]),
// h1r[k][f] = relu(b1[f] + (agg3[k]*dis[k]) @ W1), dis[k] = agg3[k].w.
__global__ __launch_bounds__(128, 5) void k_gemmS(const float* __restrict__ W1,
                                                  const float* __restrict__ b1) {
    __shared__ __align__(16) float sC[2][TK * G_NUM];   // 2 x 6.4 KB
    __shared__ __align__(16) float sh[2][TK * D];       // 2 x 12.8 KB
    __shared__ __align__(16) float sW[3 * D];
    __shared__ __align__(16) float sb[D];
    int tid = threadIdx.x;
    int g0 = (tid >> 4) * 8;        // 8 groups of 8 graphs
    int f0 = (tid & 15) * 8;        // 16 groups of 8 features
    int kbase = blockIdx.x * KC;

    if (tid < 96) ((float4*)sW)[tid] = ((const float4*)W1)[tid];
    if (tid >= 96 && tid < 128) ((float4*)sb)[tid - 96] = ((const float4*)b1)[tid - 96];
    __syncthreads();               // sW/sb must be visible to ALL threads before h_stage

    // stage h tile 'buf' for k-rows [k0, k0+TK): direct LDG of agg3 (L1-broadcast)
    auto h_stage = [&](int buf, int k0) {
        for (int i = tid; i < TK * D / 4; i += 128) {
            int r = i >> 5;                 // 32 float4 per h row
            int c = (i & 31) * 4;
            float4 ag = ((const float4*)g_agg3)[k0 + r];
            float dv = ag.w;
            float a0 = ag.x * dv;
            float a1 = ag.y * dv;
            float a2 = ag.z * dv;
            float4 w0 = *(const float4*)(sW + 0 * D + c);
            float4 w1 = *(const float4*)(sW + 1 * D + c);
            float4 w2 = *(const float4*)(sW + 2 * D + c);
            float4 bv = *(const float4*)(sb + c);
            float4 hv;
            hv.x = dv * fmaxf(bv.x + a0 * w0.x + a1 * w1.x + a2 * w2.x, 0.0f);
            hv.y = dv * fmaxf(bv.y + a0 * w0.y + a1 * w1.y + a2 * w2.y, 0.0f);
            hv.z = dv * fmaxf(bv.z + a0 * w0.z + a1 * w1.z + a2 * w2.z, 0.0f);
            hv.w = dv * fmaxf(bv.w + a0 * w0.w + a1 * w1.w + a2 * w2.w, 0.0f);
            ((float4*)sh[buf])[i] = hv;
        }
    };
    auto c_issue = [&](int buf, int k0) {
        const float4* Cg = (const float4*)(g_C + (size_t)k0 * G_NUM);
        for (int i = tid; i < TK * G_NUM / 4; i += 128)
            cpa16(&((float4*)sC[buf])[i], &Cg[i]);
        CP_COMMIT();
    };

    unsigned long long acc[8][4];
#pragma unroll
    for (int i = 0; i < 8; i++)
#pragma unroll
        for (int p = 0; p < 4; p++) acc[i][p] = 0ULL;

    // prologue: tile 0
    c_issue(0, kbase);
    h_stage(0, kbase);
    CP_WAIT0();
    __syncthreads();

#pragma unroll 1
    for (int t = 0; t < NT; t++) {
        int cur = t & 1, nxt = cur ^ 1;
        if (t + 1 < NT) c_issue(nxt, kbase + (t + 1) * TK);

#pragma unroll 1
        for (int kk = 0; kk < TK; kk++) {
            float4 ca = *(const float4*)(sC[cur] + kk * G_NUM + g0);
            float4 cb = *(const float4*)(sC[cur] + kk * G_NUM + g0 + 4);
            ulonglong2 h01 = *(const ulonglong2*)(sh[cur] + kk * D + f0);
            ulonglong2 h23 = *(const ulonglong2*)(sh[cur] + kk * D + f0 + 4);
            unsigned long long hp[4] = {h01.x, h01.y, h23.x, h23.y};
            unsigned long long cp[8];
            cp[0] = packf2(ca.x); cp[1] = packf2(ca.y);
            cp[2] = packf2(ca.z); cp[3] = packf2(ca.w);
            cp[4] = packf2(cb.x); cp[5] = packf2(cb.y);
            cp[6] = packf2(cb.z); cp[7] = packf2(cb.w);
#pragma unroll
            for (int i = 0; i < 8; i++)
#pragma unroll
                for (int p = 0; p < 4; p++) fma2(acc[i][p], cp[i], hp[p]);
        }

        if (t + 1 < NT) {
            h_stage(nxt, kbase + (t + 1) * TK);
            CP_WAIT0();
        }
        __syncthreads();
    }

    // epilogue: atomic reduce into g_T
#pragma unroll
    for (int i = 0; i < 8; i++) {
        float2 v0 = *(float2*)&acc[i][0];
        float2 v1 = *(float2*)&acc[i][1];
        float2 v2 = *(float2*)&acc[i][2];
        float2 v3 = *(float2*)&acc[i][3];
        red_add_v4(&g_T[(g0 + i) * D + f0],     make_float4(v0.x, v0.y, v1.x, v1.y));
        red_add_v4(&g_T[(g0 + i) * D + f0 + 4], make_float4(v2.x, v2.y, v3.x, v3.y));
    }
}

// ---------------- mean + @W2+b2 + @Wf+bf  (block per graph, 512 thr) ----------------
__global__ __launch_bounds__(512) void k_pwq(const float* __restrict__ W2,
                                             const float* __restrict__ b2,
                                             const float* __restrict__ Wf,
                                             const float* __restrict__ bf,
                                             float* __restrict__ q) {
    __shared__ float sT[D];
    __shared__ float sge[D];
    int g = blockIdx.x;
    int tid = threadIdx.x;    // 512

    if (tid < D) {
        float cnt = fmaxf((float)g_cntg[g], 1.0f);
        sT[tid] = g_T[g * D + tid] / cnt;
    }
    __syncthreads();

    if (tid < D) {
        float acc = b2[tid];
#pragma unroll 16
        for (int k = 0; k < D; k++) acc += sT[k] * W2[k * D + tid];
        sge[tid] = acc;
    }
    __syncthreads();

    {
        int a = tid;            // 512 threads == A_DIM outputs
        float acc = bf[a];
#pragma unroll 16
        for (int k = 0; k < D; k++) acc += sge[k] * Wf[k * A_DIM + a];
        q[g * A_DIM + a] = acc;
    }
}

// ---------------- launch ----------------
extern "C" void kernel_launch(void* const* d_in, const int* in_sizes, int n_in,
                              void* d_out, int out_size) {
    const float* x     = (const float*)d_in[0];
    const int*   ei    = (const int*)  d_in[1];
    const int*   batch = (const int*)  d_in[2];
    const float* W1    = (const float*)d_in[3];
    const float* b1    = (const float*)d_in[4];
    const float* W2    = (const float*)d_in[5];
    const float* b2    = (const float*)d_in[6];
    const float* Wf    = (const float*)d_in[7];
    const float* bf    = (const float*)d_in[8];
    float* q = (float*)d_out;

    const int* src = ei;
    const int* dst = ei + N_EDGES;

    void *pc, *pg, *pt;
    cudaGetSymbolAddress(&pc, g_cnt);
    cudaGetSymbolAddress(&pg, g_cntg);
    cudaGetSymbolAddress(&pt, g_T);

    cudaMemsetAsync(pc, 0, N_NODES * sizeof(int));
    cudaMemsetAsync(pg, 0, G_NUM * sizeof(int));
    cudaMemsetAsync(pt, 0, G_NUM * D * sizeof(float));

    k_hist<<<(N_EDGES + 255) / 256, 256>>>(dst);
    k_dis_init<<<(N_NODES * 16 + 255) / 256, 256>>>(x, batch);
    k_edge<<<(N_EDGES + 255) / 256, 256>>>(src, dst);
    k_gemmS<<<NBLK, 128>>>(W1, b1);
    k_pwq<<<G_NUM, 512>>>(W2, b2, Wf, bf, q);
}